// round 1
// baseline (speedup 1.0000x reference)
#include <cuda_runtime.h>
#include <cuda_bf16.h>
#include <cstdint>

#define D 512
#define NMAX 8192
#define KC 32          // K chunk per smem stage
#define LDS 40         // KC + 8 pad (bf16 units) -> conflict-free ldmatrix

// Scratch (no allocations allowed)
__device__ __nv_bfloat16 g_xn[(size_t)NMAX * D];
__device__ __nv_bfloat16 g_yn[(size_t)NMAX * D];
__device__ float g_rowsum[NMAX];
__device__ float g_colsum[NMAX];
__device__ float g_diag;

// ---------------------------------------------------------------------------
__global__ void zero_kernel(int n) {
    int i = blockIdx.x * blockDim.x + threadIdx.x;
    if (i < n) { g_rowsum[i] = 0.f; g_colsum[i] = 0.f; }
    if (i == 0) g_diag = 0.f;
}

// One block per row (x rows first, then y rows). 128 threads * 4 floats = 512.
__global__ void normalize_kernel(const float* __restrict__ x,
                                 const float* __restrict__ y, int n) {
    int b = blockIdx.x;
    const float* src = (b < n) ? x : y;
    __nv_bfloat16* dst = (b < n) ? g_xn : g_yn;
    int row = (b < n) ? b : (b - n);

    float4 v = ((const float4*)(src + (size_t)row * D))[threadIdx.x];
    float ss = v.x*v.x + v.y*v.y + v.z*v.z + v.w*v.w;
    #pragma unroll
    for (int o = 16; o; o >>= 1) ss += __shfl_xor_sync(0xffffffffu, ss, o);
    __shared__ float sred[4];
    if ((threadIdx.x & 31) == 0) sred[threadIdx.x >> 5] = ss;
    __syncthreads();
    float tot = sred[0] + sred[1] + sred[2] + sred[3];
    float inv = 1.f / fmaxf(sqrtf(tot), 1e-8f);

    __nv_bfloat162 p0 = __floats2bfloat162_rn(v.x * inv, v.y * inv);
    __nv_bfloat162 p1 = __floats2bfloat162_rn(v.z * inv, v.w * inv);
    __nv_bfloat162* d = (__nv_bfloat162*)(dst + (size_t)row * D + threadIdx.x * 4);
    d[0] = p0; d[1] = p1;
}

// ---------------------------------------------------------------------------
__device__ __forceinline__ void cp16(uint32_t s, const void* g) {
    asm volatile("cp.async.cg.shared.global [%0], [%1], 16;\n" :: "r"(s), "l"(g));
}
__device__ __forceinline__ void ldm4(uint32_t* r, uint32_t s) {
    asm volatile("ldmatrix.sync.aligned.m8n8.x4.shared.b16 {%0,%1,%2,%3}, [%4];\n"
                 : "=r"(r[0]), "=r"(r[1]), "=r"(r[2]), "=r"(r[3]) : "r"(s));
}
__device__ __forceinline__ void mma16816(float* c, const uint32_t* a, const uint32_t* b) {
    asm volatile("mma.sync.aligned.m16n8k16.row.col.f32.bf16.bf16.f32 "
                 "{%0,%1,%2,%3}, {%4,%5,%6,%7}, {%8,%9}, {%0,%1,%2,%3};\n"
                 : "+f"(c[0]), "+f"(c[1]), "+f"(c[2]), "+f"(c[3])
                 : "r"(a[0]), "r"(a[1]), "r"(a[2]), "r"(a[3]),
                   "r"(b[0]), "r"(b[1]));
}

// 128x128 output tile per CTA. 8 warps: warp_m = wid&3 (32 rows), warp_n = wid>>2 (64 cols).
// Fused epilogue: exp + row/col partial sums, shuffle-reduced, atomically merged.
__global__ __launch_bounds__(256)
void gemm_kernel() {
    __shared__ alignas(16) __nv_bfloat16 As[2][128 * LDS];
    __shared__ alignas(16) __nv_bfloat16 Bs[2][128 * LDS];

    const int bi = blockIdx.y, bj = blockIdx.x;
    const int tid = threadIdx.x;
    const int lane = tid & 31, wid = tid >> 5;
    const int wm = wid & 3, wn = wid >> 2;

    const __nv_bfloat16* Ag = g_xn + (size_t)bi * 128 * D;
    const __nv_bfloat16* Bg = g_yn + (size_t)bj * 128 * D;

    const uint32_t as0 = (uint32_t)__cvta_generic_to_shared(&As[0][0]);
    const uint32_t as1 = (uint32_t)__cvta_generic_to_shared(&As[1][0]);
    const uint32_t bs0 = (uint32_t)__cvta_generic_to_shared(&Bs[0][0]);
    const uint32_t bs1 = (uint32_t)__cvta_generic_to_shared(&Bs[1][0]);

    // Each thread copies two 16B segments of each tile (128 rows * 4 segs = 512 segs).
    const int r0 = tid >> 2,        k0s = tid & 3;
    const int r1 = (tid + 256) >> 2, k1s = (tid + 256) & 3;

    float acc[2][8][4];
    #pragma unroll
    for (int i = 0; i < 2; i++)
        #pragma unroll
        for (int j = 0; j < 8; j++)
            #pragma unroll
            for (int k = 0; k < 4; k++) acc[i][j][k] = 0.f;

    auto issue = [&](int kc, uint32_t as, uint32_t bs) {
        cp16(as + (uint32_t)(r0 * LDS + k0s * 8) * 2, Ag + r0 * D + kc * KC + k0s * 8);
        cp16(as + (uint32_t)(r1 * LDS + k1s * 8) * 2, Ag + r1 * D + kc * KC + k1s * 8);
        cp16(bs + (uint32_t)(r0 * LDS + k0s * 8) * 2, Bg + r0 * D + kc * KC + k0s * 8);
        cp16(bs + (uint32_t)(r1 * LDS + k1s * 8) * 2, Bg + r1 * D + kc * KC + k1s * 8);
        asm volatile("cp.async.commit_group;\n");
    };

    issue(0, as0, bs0);

    const int g = lane >> 3, rr = lane & 7;   // ldmatrix lane addressing
    const int NCHUNK = D / KC;                // 16

    for (int kc = 0; kc < NCHUNK; kc++) {
        uint32_t asb = (kc & 1) ? as1 : as0;
        uint32_t bsb = (kc & 1) ? bs1 : bs0;
        if (kc + 1 < NCHUNK) {
            issue(kc + 1, (kc & 1) ? as0 : as1, (kc & 1) ? bs0 : bs1);
            asm volatile("cp.async.wait_group 1;\n");
        } else {
            asm volatile("cp.async.wait_group 0;\n");
        }
        __syncthreads();

        #pragma unroll
        for (int ks = 0; ks < KC / 16; ks++) {
            const int k0 = ks * 16;
            uint32_t a[2][4];
            #pragma unroll
            for (int mt = 0; mt < 2; mt++) {
                int arow = wm * 32 + mt * 16 + (g & 1) * 8 + rr;
                int acol = k0 + (g >> 1) * 8;
                ldm4(a[mt], asb + (uint32_t)(arow * LDS + acol) * 2);
            }
            uint32_t b[8][2];
            #pragma unroll
            for (int ntp = 0; ntp < 4; ntp++) {
                int brow = wn * 64 + ntp * 16 + (g >> 1) * 8 + rr;
                int bcol = k0 + (g & 1) * 8;
                uint32_t t[4];
                ldm4(t, bsb + (uint32_t)(brow * LDS + bcol) * 2);
                b[2 * ntp][0] = t[0];     b[2 * ntp][1] = t[1];
                b[2 * ntp + 1][0] = t[2]; b[2 * ntp + 1][1] = t[3];
            }
            #pragma unroll
            for (int mt = 0; mt < 2; mt++)
                #pragma unroll
                for (int nt = 0; nt < 8; nt++)
                    mma16816(acc[mt][nt], a[mt], b[nt]);
        }
        __syncthreads();
    }

    // ---- fused epilogue: logits = 2*cos; streaming exp-sums, no S in memory ----
    float rsum[2][2] = {{0.f, 0.f}, {0.f, 0.f}};  // [mt][row-half]
    float dsum = 0.f;
    const bool diagblk = (bi == bj);
    const int mrow0 = wm * 32 + (lane >> 2);
    const int ncol0 = wn * 64 + 2 * (lane & 3);

    #pragma unroll
    for (int nt = 0; nt < 8; nt++) {
        float cs0 = 0.f, cs1 = 0.f;
        #pragma unroll
        for (int mt = 0; mt < 2; mt++) {
            float* c = acc[mt][nt];
            float l00 = 2.f * c[0], l01 = 2.f * c[1];
            float l10 = 2.f * c[2], l11 = 2.f * c[3];
            float e00 = __expf(l00), e01 = __expf(l01);
            float e10 = __expf(l10), e11 = __expf(l11);
            rsum[mt][0] += e00 + e01;
            rsum[mt][1] += e10 + e11;
            cs0 += e00 + e10;
            cs1 += e01 + e11;
            if (diagblk) {
                int m0 = mrow0 + mt * 16;
                int n0 = ncol0 + nt * 8;
                if (m0 == n0)         dsum += l00;
                if (m0 == n0 + 1)     dsum += l01;
                if (m0 + 8 == n0)     dsum += l10;
                if (m0 + 8 == n0 + 1) dsum += l11;
            }
        }
        // reduce column partials over lane>>2 (rows)
        #pragma unroll
        for (int o = 4; o < 32; o <<= 1) {
            cs0 += __shfl_xor_sync(0xffffffffu, cs0, o);
            cs1 += __shfl_xor_sync(0xffffffffu, cs1, o);
        }
        if (lane < 4) {
            int col = bj * 128 + wn * 64 + nt * 8 + 2 * lane;
            atomicAdd(&g_colsum[col],     cs0);
            atomicAdd(&g_colsum[col + 1], cs1);
        }
    }
    // reduce row partials over lane&3 (cols)
    #pragma unroll
    for (int mt = 0; mt < 2; mt++) {
        #pragma unroll
        for (int h = 0; h < 2; h++) {
            float v = rsum[mt][h];
            v += __shfl_xor_sync(0xffffffffu, v, 1);
            v += __shfl_xor_sync(0xffffffffu, v, 2);
            if ((lane & 3) == 0) {
                int row = bi * 128 + wm * 32 + mt * 16 + h * 8 + (lane >> 2);
                atomicAdd(&g_rowsum[row], v);
            }
        }
    }
    if (diagblk) {
        #pragma unroll
        for (int o = 16; o; o >>= 1) dsum += __shfl_xor_sync(0xffffffffu, dsum, o);
        if (lane == 0) atomicAdd(&g_diag, dsum);
    }
}

// ---------------------------------------------------------------------------
__global__ void finalize_kernel(float* out, int n) {
    float s = 0.f;
    for (int i = threadIdx.x; i < n; i += blockDim.x)
        s += logf(g_rowsum[i]) + logf(g_colsum[i]);
    #pragma unroll
    for (int o = 16; o; o >>= 1) s += __shfl_xor_sync(0xffffffffu, s, o);
    __shared__ float red[32];
    if ((threadIdx.x & 31) == 0) red[threadIdx.x >> 5] = s;
    __syncthreads();
    if (threadIdx.x < 32) {
        float v = (threadIdx.x < (blockDim.x >> 5)) ? red[threadIdx.x] : 0.f;
        #pragma unroll
        for (int o = 16; o; o >>= 1) v += __shfl_xor_sync(0xffffffffu, v, o);
        if (threadIdx.x == 0)
            out[0] = v / (2.f * (float)n) - g_diag / (float)n;
    }
}

// ---------------------------------------------------------------------------
extern "C" void kernel_launch(void* const* d_in, const int* in_sizes, int n_in,
                              void* d_out, int out_size) {
    const float* x = (const float*)d_in[0];
    const float* y = (const float*)d_in[1];
    int n = in_sizes[0] / D;   // 8192

    zero_kernel<<<(n + 255) / 256, 256>>>(n);
    normalize_kernel<<<2 * n, 128>>>(x, y, n);
    gemm_kernel<<<dim3(n / 128, n / 128), 256>>>();
    finalize_kernel<<<1, 1024>>>((float*)d_out, n);
}

// round 3
// speedup vs baseline: 1.1429x; 1.1429x over previous
#include <cuda_runtime.h>
#include <cuda_bf16.h>
#include <cstdint>

#define D 512
#define NMAX 8192
#define KC 64                         // K elems per stage
#define STAGE 49152                   // A:256*128B + B:128*128B
#define NSTG 3
#define DYN_SMEM (NSTG * STAGE + 1024)

// Scratch (no device allocations allowed)
__device__ __nv_bfloat16 g_xn[(size_t)NMAX * D];
__device__ __nv_bfloat16 g_yn[(size_t)NMAX * D];
__device__ float g_rowsum[NMAX];
__device__ float g_colsum[NMAX];
__device__ float g_diag;
__device__ float g_part;
__device__ unsigned int g_cnt;

// ---------------------------------------------------------------------------
__device__ __forceinline__ uint32_t smem_u32(const void* p) {
    uint32_t r;
    asm("{ .reg .u64 t; cvta.to.shared.u64 t, %1; cvt.u32.u64 %0, t; }"
        : "=r"(r) : "l"(p));
    return r;
}
__device__ __forceinline__ void cp16(uint32_t s, const void* g) {
    asm volatile("cp.async.cg.shared.global [%0], [%1], 16;\n" :: "r"(s), "l"(g));
}
__device__ __forceinline__ uint32_t sw(uint32_t off) {   // SW128 XOR swizzle
    return off ^ ((off >> 3) & 0x70);
}
__device__ __forceinline__ void ldm4(uint32_t* r, uint32_t s) {
    asm volatile("ldmatrix.sync.aligned.m8n8.x4.shared.b16 {%0,%1,%2,%3}, [%4];\n"
                 : "=r"(r[0]), "=r"(r[1]), "=r"(r[2]), "=r"(r[3]) : "r"(s));
}
__device__ __forceinline__ void mma16816(float* c, const uint32_t* a, const uint32_t* b) {
    asm volatile("mma.sync.aligned.m16n8k16.row.col.f32.bf16.bf16.f32 "
                 "{%0,%1,%2,%3}, {%4,%5,%6,%7}, {%8,%9}, {%0,%1,%2,%3};\n"
                 : "+f"(c[0]), "+f"(c[1]), "+f"(c[2]), "+f"(c[3])
                 : "r"(a[0]), "r"(a[1]), "r"(a[2]), "r"(a[3]),
                   "r"(b[0]), "r"(b[1]));
}

// ---------------------------------------------------------------------------
// normalize + fused accumulator zeroing. One block per row, x rows then y.
__global__ void normalize_kernel(const float* __restrict__ x,
                                 const float* __restrict__ y, int n) {
    int b = blockIdx.x;
    if (threadIdx.x == 0) {
        if (b < n) { g_rowsum[b] = 0.f; g_colsum[b] = 0.f; }
        if (b == 0) { g_diag = 0.f; g_part = 0.f; g_cnt = 0u; }
    }
    const float* src = (b < n) ? x : y;
    __nv_bfloat16* dst = (b < n) ? g_xn : g_yn;
    int row = (b < n) ? b : (b - n);

    float4 v = ((const float4*)(src + (size_t)row * D))[threadIdx.x];
    float ss = v.x*v.x + v.y*v.y + v.z*v.z + v.w*v.w;
    #pragma unroll
    for (int o = 16; o; o >>= 1) ss += __shfl_xor_sync(0xffffffffu, ss, o);
    __shared__ float sred[4];
    if ((threadIdx.x & 31) == 0) sred[threadIdx.x >> 5] = ss;
    __syncthreads();
    float tot = sred[0] + sred[1] + sred[2] + sred[3];
    float inv = 1.f / fmaxf(sqrtf(tot), 1e-8f);

    __nv_bfloat162 p0 = __floats2bfloat162_rn(v.x * inv, v.y * inv);
    __nv_bfloat162 p1 = __floats2bfloat162_rn(v.z * inv, v.w * inv);
    __nv_bfloat162* d = (__nv_bfloat162*)(dst + (size_t)row * D + threadIdx.x * 4);
    d[0] = p0; d[1] = p1;
}

// ---------------------------------------------------------------------------
// 256(M) x 128(N) tile per CTA, 8 warps in 4(M) x 2(N), warp tile 64x64.
// 3-stage cp.async pipeline, KC=64 per stage. Fused streaming-softmax epilogue.
__global__ void __launch_bounds__(256) gemm_kernel() {
    extern __shared__ char dyn_raw[];
    const int tid = threadIdx.x, lane = tid & 31, wid = tid >> 5;
    const int wm = wid & 3, wn = wid >> 2;
    const int bi = blockIdx.y, bj = blockIdx.x;
    const int g = lane >> 3, rr = lane & 7;

    uint32_t dynb = (smem_u32(dyn_raw) + 1023u) & ~1023u;

    const __nv_bfloat16* Ag = g_xn + (size_t)bi * 256 * D;
    const __nv_bfloat16* Bg = g_yn + (size_t)bj * 128 * D;

    auto issue = [&](int kc, uint32_t stage) {
        #pragma unroll
        for (int it = 0; it < 8; it++) {                  // A: 256 rows x 8 segs
            int i = tid + it * 256; int r = i >> 3, j = i & 7;
            uint32_t off = (uint32_t)(r * 128 + j * 16);
            cp16(stage + sw(off), Ag + r * D + kc * KC + j * 8);
        }
        #pragma unroll
        for (int it = 0; it < 4; it++) {                  // B: 128 rows x 8 segs
            int i = tid + it * 256; int r = i >> 3, j = i & 7;
            uint32_t off = (uint32_t)(r * 128 + j * 16);
            cp16(stage + 32768 + sw(off), Bg + r * D + kc * KC + j * 8);
        }
        asm volatile("cp.async.commit_group;");
    };

    issue(0, dynb);
    issue(1, dynb + STAGE);
    issue(2, dynb + 2 * STAGE);

    float acc[4][8][4];
    #pragma unroll
    for (int i = 0; i < 4; i++)
        #pragma unroll
        for (int j = 0; j < 8; j++)
            #pragma unroll
            for (int k = 0; k < 4; k++) acc[i][j][k] = 0.f;

    int sidx = 0;
    for (int kc = 0; kc < 8; kc++) {
        if (kc < 6)      asm volatile("cp.async.wait_group 2;");
        else if (kc == 6) asm volatile("cp.async.wait_group 1;");
        else              asm volatile("cp.async.wait_group 0;");
        __syncthreads();

        uint32_t sA = dynb + sidx * STAGE;
        uint32_t sB = sA + 32768;

        #pragma unroll
        for (int ks = 0; ks < 4; ks++) {
            const int k0 = ks * 16;
            uint32_t a[4][4];
            #pragma unroll
            for (int mt = 0; mt < 4; mt++) {
                int arow = wm * 64 + mt * 16 + (g & 1) * 8 + rr;
                int acol = k0 + (g >> 1) * 8;
                ldm4(a[mt], sA + sw((uint32_t)(arow * 128 + acol * 2)));
            }
            uint32_t b[8][2];
            #pragma unroll
            for (int ntp = 0; ntp < 4; ntp++) {
                int brow = wn * 64 + ntp * 16 + (g >> 1) * 8 + rr;
                int bcol = k0 + (g & 1) * 8;
                uint32_t t[4];
                ldm4(t, sB + sw((uint32_t)(brow * 128 + bcol * 2)));
                b[2 * ntp][0] = t[0];     b[2 * ntp][1] = t[1];
                b[2 * ntp + 1][0] = t[2]; b[2 * ntp + 1][1] = t[3];
            }
            #pragma unroll
            for (int mt = 0; mt < 4; mt++)
                #pragma unroll
                for (int nt = 0; nt < 8; nt++)
                    mma16816(acc[mt][nt], a[mt], b[nt]);
        }
        __syncthreads();
        if (kc + 3 < 8) issue(kc + 3, dynb + sidx * STAGE);
        sidx = (sidx == 2) ? 0 : sidx + 1;
    }

    // ---- fused epilogue: logits = 2*cos; streaming exp-sums ----
    const bool hasdiag = ((bj >> 1) == bi);
    const int mrow_loc = wm * 64 + (lane >> 2);           // local row (within 256)
    const int ncol_loc = wn * 64 + 2 * (lane & 3);        // local col (within 128)
    const int rowdelta = bi * 256 - bj * 128;             // row_g - col_g offset

    float rsum[4][2];
    #pragma unroll
    for (int i = 0; i < 4; i++) { rsum[i][0] = 0.f; rsum[i][1] = 0.f; }
    float dsum = 0.f;

    #pragma unroll
    for (int nt = 0; nt < 8; nt++) {
        float cs0 = 0.f, cs1 = 0.f;
        #pragma unroll
        for (int mt = 0; mt < 4; mt++) {
            float* c = acc[mt][nt];
            float l00 = 2.f * c[0], l01 = 2.f * c[1];
            float l10 = 2.f * c[2], l11 = 2.f * c[3];
            float e00 = __expf(l00), e01 = __expf(l01);
            float e10 = __expf(l10), e11 = __expf(l11);
            rsum[mt][0] += e00 + e01;
            rsum[mt][1] += e10 + e11;
            cs0 += e00 + e10;
            cs1 += e01 + e11;
            if (hasdiag) {
                int m0 = mrow_loc + mt * 16 + rowdelta;   // row_g - bj*128
                int n0 = ncol_loc + nt * 8;
                if (m0 == n0)         dsum += l00;
                if (m0 == n0 + 1)     dsum += l01;
                if (m0 + 8 == n0)     dsum += l10;
                if (m0 + 8 == n0 + 1) dsum += l11;
            }
        }
        #pragma unroll
        for (int o = 4; o < 32; o <<= 1) {
            cs0 += __shfl_xor_sync(0xffffffffu, cs0, o);
            cs1 += __shfl_xor_sync(0xffffffffu, cs1, o);
        }
        if (lane < 4) {
            int col = bj * 128 + wn * 64 + nt * 8 + 2 * lane;
            atomicAdd(&g_colsum[col],     cs0);
            atomicAdd(&g_colsum[col + 1], cs1);
        }
    }
    #pragma unroll
    for (int mt = 0; mt < 4; mt++) {
        #pragma unroll
        for (int h = 0; h < 2; h++) {
            float v = rsum[mt][h];
            v += __shfl_xor_sync(0xffffffffu, v, 1);
            v += __shfl_xor_sync(0xffffffffu, v, 2);
            if ((lane & 3) == 0) {
                int row = bi * 256 + wm * 64 + mt * 16 + h * 8 + (lane >> 2);
                atomicAdd(&g_rowsum[row], v);
            }
        }
    }
    if (hasdiag) {
        #pragma unroll
        for (int o = 16; o; o >>= 1) dsum += __shfl_xor_sync(0xffffffffu, dsum, o);
        if (lane == 0) atomicAdd(&g_diag, dsum);
    }
}

// ---------------------------------------------------------------------------
__global__ void finalize_kernel(float* out, int n) {
    float s = 0.f;
    for (int i = blockIdx.x * blockDim.x + threadIdx.x; i < n;
         i += gridDim.x * blockDim.x)
        s += logf(g_rowsum[i]) + logf(g_colsum[i]);
    #pragma unroll
    for (int o = 16; o; o >>= 1) s += __shfl_xor_sync(0xffffffffu, s, o);
    __shared__ float red[8];
    if ((threadIdx.x & 31) == 0) red[threadIdx.x >> 5] = s;
    __syncthreads();
    if (threadIdx.x == 0) {
        float v = 0.f;
        #pragma unroll
        for (int w = 0; w < 8; w++) v += red[w];
        atomicAdd(&g_part, v);
        __threadfence();
        unsigned t = atomicAdd(&g_cnt, 1u);
        if (t == gridDim.x - 1) {
            float tot = atomicAdd(&g_part, 0.f);
            out[0] = tot / (2.f * (float)n) - g_diag / (float)n;
        }
    }
}

// ---------------------------------------------------------------------------
extern "C" void kernel_launch(void* const* d_in, const int* in_sizes, int n_in,
                              void* d_out, int out_size) {
    const float* x = (const float*)d_in[0];
    const float* y = (const float*)d_in[1];
    int n = in_sizes[0] / D;   // 8192

    cudaFuncSetAttribute(gemm_kernel,
                         cudaFuncAttributeMaxDynamicSharedMemorySize, DYN_SMEM);

    normalize_kernel<<<2 * n, 128>>>(x, y, n);
    gemm_kernel<<<dim3(n / 128, n / 256), 256, DYN_SMEM>>>();
    finalize_kernel<<<16, 256>>>((float*)d_out, n);
}